// round 3
// baseline (speedup 1.0000x reference)
#include <cuda_runtime.h>
#include <cstdint>

#define NPTS  5760
#define BATCH 4
#define CT    640            // columns per tile
#define NCT   9              // 5760 / 640
#define RT    240            // rows per block
#define NRT   24             // 5760 / 240
#define WARPS 8
#define TPB   256
#define RPW   30             // rows per warp (240 / 8)
#define EPL   20             // elements per lane (640 / 32)
#define DPTH  4              // cp.async ring depth (rows staged per warp)
#define ROWB  (CT * 4)       // 2560 bytes per staged row
#define TEMPF 100.0f
#define NEGV  -1e30f
#define TH_OFF 0.30f         // exp cutoff: e^(-30) ~ 1e-13 relative

// -------- scratch (static device globals; no allocation allowed) --------
__device__ float g_rowpart[BATCH * NCT * NPTS * 8];   // per (b,tile,row): m,s,px,py,pz,argcol
__device__ float g_colV[BATCH * NRT * NPTS];          // per (b,rowtile,col): best value
__device__ int   g_colR[BATCH * NRT * NPTS];          // per (b,rowtile,col): best row
__device__ float g_p2[BATCH * NPTS * 4];              // points2 (xyz, pad)
__device__ int   g_i21[BATCH * NPTS];                 // ind2to1
__device__ int   g_i12[BATCH * NPTS];                 // ind1to2
__device__ unsigned g_ctr;                            // ticket counter (self-resetting)

// -------- cp.async helpers --------
__device__ __forceinline__ void cp16(uint32_t sdst, const void* gsrc) {
    asm volatile("cp.async.cg.shared.global [%0], [%1], 16;" :: "r"(sdst), "l"(gsrc));
}
__device__ __forceinline__ void cp_commit() {
    asm volatile("cp.async.commit_group;" ::: "memory");
}
template<int N> __device__ __forceinline__ void cp_wait() {
    asm volatile("cp.async.wait_group %0;" :: "n"(N) : "memory");
}

// stage one row (5 x 16B per lane) into ring slot, one commit group
__device__ __forceinline__ void stage_row(uint32_t sdst, const float* grow, int lane) {
#pragma unroll
    for (int k = 0; k < 5; k++)
        cp16(sdst + k * 512, (const void*)(grow + k * 128 + lane * 4));
    cp_commit();
}

// ================= K1: single streaming pass over valid rows ================
extern __shared__ char dynsmem[];

__global__ void __launch_bounds__(TPB, 2) k_main(const float* __restrict__ match,
                                                 const float* __restrict__ tgt,
                                                 const int*   __restrict__ pmask)
{
    const int b    = blockIdx.z;
    const int tile = blockIdx.x;
    const int rt   = blockIdx.y;
    const int warp = threadIdx.x >> 5;
    const int lane = threadIdx.x & 31;
    const int col0 = tile * CT;
    const int row0 = rt * RT;

    const int* m1p = pmask + (size_t)(2 * b) * NPTS;
    const int* m2p = pmask + (size_t)(2 * b + 1) * NPTS;

    const uint32_t sbase = (uint32_t)__cvta_generic_to_shared(dynsmem);
    const uint32_t mybuf = sbase + (uint32_t)(warp * DPTH) * ROWB + lane * 16;

    // per-lane column mask-add (m2): +0 if valid, -1e30 if masked
    float ma[EPL];
    float cbv[EPL];   // column-best value
    int   cbr[EPL];   // column-best row
#pragma unroll
    for (int k = 0; k < 5; k++) {
        int4 mm = *(const int4*)(m2p + col0 + k * 128 + lane * 4);
        ma[4*k+0] = mm.x ? 0.f : NEGV;
        ma[4*k+1] = mm.y ? 0.f : NEGV;
        ma[4*k+2] = mm.z ? 0.f : NEGV;
        ma[4*k+3] = mm.w ? 0.f : NEGV;
    }
#pragma unroll
    for (int e = 0; e < EPL; e++) { cbv[e] = -INFINITY; cbr[e] = 0; }

    const float* tgx = tgt + (size_t)(b * 3 + 0) * NPTS;
    const float* tgy = tgt + (size_t)(b * 3 + 1) * NPTS;
    const float* tgz = tgt + (size_t)(b * 3 + 2) * NPTS;

    const int rbeg = row0 + warp * RPW;
    bool vb = (lane < RPW) ? (m1p[rbeg + lane] != 0) : false;
    const unsigned mbits = __ballot_sync(0xffffffffu, vb);
    const int nval = __popc(mbits);

    // per-lane: index of (lane+1)-th set bit of mbits (valid for lane < nval)
    int rl = 0;
    {
        int need = lane + 1;
        for (int bb = 0; bb < RPW; bb++)
            if ((mbits >> bb) & 1u) { if (--need == 0) { rl = bb; break; } }
    }

    const float* mbase = match + ((size_t)b * NPTS) * NPTS + col0;

    // ---- prologue: stage first DPTH valid rows ----
#pragma unroll
    for (int i = 0; i < DPTH; i++) {
        if (i < nval) {
            int rr = rbeg + __shfl_sync(0xffffffffu, rl, i);
            stage_row(mybuf + (i % DPTH) * ROWB, mbase + (size_t)rr * NPTS, lane);
        } else {
            cp_commit();   // empty group keeps wait_group accounting aligned
        }
    }

    // ---- main pipeline ----
    for (int i = 0; i < nval; i++) {
        cp_wait<DPTH - 1>();   // stage i complete
        const int r = rbeg + __shfl_sync(0xffffffffu, rl, i);
        const char* buf = dynsmem + (size_t)(warp * DPTH + (i % DPTH)) * ROWB + lane * 16;

        float v[EPL];
#pragma unroll
        for (int k = 0; k < 5; k++) {
            float4 t = *(const float4*)(buf + k * 512);
            v[4*k+0] = t.x; v[4*k+1] = t.y; v[4*k+2] = t.z; v[4*k+3] = t.w;
        }
        // column-best + masked values (tree max for short dep chain)
        float vm[EPL];
#pragma unroll
        for (int e = 0; e < EPL; e++) {
            if (v[e] > cbv[e]) { cbv[e] = v[e]; cbr[e] = r; }
            vm[e] = v[e] + ma[e];
        }
        float m0 = fmaxf(fmaxf(fmaxf(vm[0], vm[1]), fmaxf(vm[2], vm[3])),
                         fmaxf(fmaxf(vm[4], vm[5]), fmaxf(vm[6], vm[7])));
        float m1v = fmaxf(fmaxf(fmaxf(vm[8], vm[9]), fmaxf(vm[10], vm[11])),
                          fmaxf(fmaxf(vm[12], vm[13]), fmaxf(vm[14], vm[15])));
        float m2v = fmaxf(fmaxf(vm[16], vm[17]), fmaxf(vm[18], vm[19]));
        float lm = fmaxf(fmaxf(m0, m1v), m2v);

        float wm = lm;
#pragma unroll
        for (int o = 16; o; o >>= 1) wm = fmaxf(wm, __shfl_xor_sync(0xffffffffu, wm, o));
        const float th = wm - TH_OFF;

        float s = 0.f, px = 0.f, py = 0.f, pz = 0.f;
        int bc = 0x7fffffff;
        const unsigned bal = __ballot_sync(0xffffffffu, lm > th);
        if (lm > th) {
#pragma unroll
            for (int e = 0; e < EPL; e++) {
                if (vm[e] > th) {
                    float w = __expf((vm[e] - wm) * TEMPF);
                    int c = col0 + (e >> 2) * 128 + lane * 4 + (e & 3);
                    s  += w;
                    px += w * tgx[c];
                    py += w * tgy[c];
                    pz += w * tgz[c];
                    if (vm[e] == wm) bc = min(bc, c);
                }
            }
        }
        if (__popc(bal) == 1) {
            // single contributing lane: broadcast instead of butterfly (5 SHFL vs 25)
            int sl = __ffs(bal) - 1;
            s  = __shfl_sync(0xffffffffu, s,  sl);
            px = __shfl_sync(0xffffffffu, px, sl);
            py = __shfl_sync(0xffffffffu, py, sl);
            pz = __shfl_sync(0xffffffffu, pz, sl);
            bc = __shfl_sync(0xffffffffu, bc, sl);
        } else {
#pragma unroll
            for (int o = 16; o; o >>= 1) {
                s  += __shfl_xor_sync(0xffffffffu, s,  o);
                px += __shfl_xor_sync(0xffffffffu, px, o);
                py += __shfl_xor_sync(0xffffffffu, py, o);
                pz += __shfl_xor_sync(0xffffffffu, pz, o);
                bc  = min(bc, __shfl_xor_sync(0xffffffffu, bc, o));
            }
        }
        if (lane == 0) {
            float* out = g_rowpart + ((size_t)(b * NCT + tile) * NPTS + r) * 8;
            *(float4*)(out)     = make_float4(wm, s, px, py);
            *(float4*)(out + 4) = make_float4(pz, __int_as_float(bc), 0.f, 0.f);
        }

        // stage row i+DPTH (buffer (i%DPTH) is now free)
        int j = i + DPTH;
        if (j < nval) {
            int rr = rbeg + __shfl_sync(0xffffffffu, rl, j);
            stage_row(mybuf + (j % DPTH) * ROWB, mbase + (size_t)rr * NPTS, lane);
        } else {
            cp_commit();
        }
    }
    cp_wait<0>();        // drain before smem reuse
    __syncthreads();

    // block-level column-best merge, aliased into the (now idle) ring buffer
    float* sv = (float*)dynsmem;                       // [WARPS][CT]
    int*   sr = (int*)(dynsmem + WARPS * CT * 4);      // [WARPS][CT]
#pragma unroll
    for (int e = 0; e < EPL; e++) {
        int cl = (e >> 2) * 128 + lane * 4 + (e & 3);
        sv[warp * CT + cl] = cbv[e];
        sr[warp * CT + cl] = cbr[e];
    }
    __syncthreads();
    for (int c = threadIdx.x; c < CT; c += TPB) {
        float bv = -INFINITY; int br = 0;
#pragma unroll
        for (int w = 0; w < WARPS; w++) {
            float vv = sv[w * CT + c];
            if (vv > bv) { bv = vv; br = sr[w * CT + c]; }
        }
        size_t o = (size_t)(b * NRT + rt) * NPTS + col0 + c;
        g_colV[o] = bv;
        g_colR[o] = br;
    }
}

// ========== K2: merge tiles, then last block computes loss + final sum ======
__global__ void __launch_bounds__(TPB) k_merge_loss(const float* __restrict__ src,
                                                    const float* __restrict__ wts,
                                                    const float* __restrict__ Tiv,
                                                    const int*   __restrict__ pmask,
                                                    float* __restrict__ out)
{
    const int gid = blockIdx.x * TPB + threadIdx.x;
    const int total = BATCH * NPTS;

    if (gid < total) {
        const int b = gid / NPTS, r = gid - b * NPTS;
        if (pmask[(size_t)(2 * b) * NPTS + r]) {
            float4 A[NCT], Bv[NCT];
#pragma unroll
            for (int t = 0; t < NCT; t++) {
                const float* base = g_rowpart + ((size_t)(b * NCT + t) * NPTS + r) * 8;
                A[t]  = *(const float4*)(base);
                Bv[t] = *(const float4*)(base + 4);
            }
            float M = -INFINITY; int argc = 0;
#pragma unroll
            for (int t = 0; t < NCT; t++)
                if (A[t].x > M) { M = A[t].x; argc = __float_as_int(Bv[t].y); }
            float S = 0.f, Px = 0.f, Py = 0.f, Pz = 0.f;
#pragma unroll
            for (int t = 0; t < NCT; t++) {
                float w = __expf((A[t].x - M) * TEMPF);
                S  += A[t].y * w;
                Px += A[t].z * w;
                Py += A[t].w * w;
                Pz += Bv[t].x * w;
            }
            float inv = 1.f / S;
            *(float4*)(g_p2 + (size_t)gid * 4) = make_float4(Px * inv, Py * inv, Pz * inv, 0.f);
            g_i21[gid] = argc;
        }
    } else if (gid < 2 * total) {
        const int g2 = gid - total;
        const int b = g2 / NPTS, c = g2 - b * NPTS;
        float bv = -INFINITY; int br = 0;
        for (int t = 0; t < NRT; t++) {
            size_t o = (size_t)(b * NRT + t) * NPTS + c;
            float vv = g_colV[o];
            if (vv > bv) { bv = vv; br = g_colR[o]; }
        }
        g_i12[g2] = br;
    }

    // ---- ticket: last block does loss + final reduction ----
    __threadfence();
    __syncthreads();
    __shared__ unsigned amlast;
    if (threadIdx.x == 0)
        amlast = (atomicAdd(&g_ctr, 1u) == gridDim.x - 1);
    __syncthreads();
    if (!amlast) return;
    __threadfence();

    __shared__ float T21[12];
    __shared__ float rs[WARPS], rd[WARPS], rc[WARPS];
    float acc = 0.f;

    for (int b = 0; b < BATCH; b++) {
        if (threadIdx.x == 0) {
            const float* Ts = Tiv + (size_t)(2 * b) * 16;
            const float* Tt = Tiv + (size_t)(2 * b + 1) * 16;
            float A[3][4];
            for (int i = 0; i < 3; i++) {
                for (int k = 0; k < 3; k++) A[i][k] = Tt[k * 4 + i];
                A[i][3] = -(Tt[0*4+i]*Tt[3] + Tt[1*4+i]*Tt[7] + Tt[2*4+i]*Tt[11]);
            }
            for (int i = 0; i < 3; i++)
                for (int j = 0; j < 4; j++)
                    T21[i*4+j] = A[i][0]*Ts[j] + A[i][1]*Ts[4+j]
                               + A[i][2]*Ts[8+j] + A[i][3]*Ts[12+j];
        }
        __syncthreads();

        const float* sx = src + (size_t)(b * 3 + 0) * NPTS;
        const float* sy = src + (size_t)(b * 3 + 1) * NPTS;
        const float* sz = src + (size_t)(b * 3 + 2) * NPTS;
        const float* w0 = wts + (size_t)(b * 6 + 0) * NPTS;
        const float* w1 = wts + (size_t)(b * 6 + 1) * NPTS;
        const float* w2 = wts + (size_t)(b * 6 + 2) * NPTS;
        const float* w3 = wts + (size_t)(b * 6 + 3) * NPTS;
        const float* w4 = wts + (size_t)(b * 6 + 4) * NPTS;
        const float* w5 = wts + (size_t)(b * 6 + 5) * NPTS;
        const int*   m1  = pmask + (size_t)(2 * b) * NPTS;
        const int*   i21 = g_i21 + b * NPTS;
        const int*   i12 = g_i12 + b * NPTS;

        float sm = 0.f, sd = 0.f, cnt = 0.f;
        for (int i = threadIdx.x; i < NPTS; i += TPB) {
            if (!m1[i]) continue;
            int j = i21[i];
            if (i12[j] != i) continue;
            float p0 = sx[i], p1 = sy[i], p2v = sz[i];
            float q0 = T21[0]*p0 + T21[1]*p1 + T21[2] *p2v + T21[3];
            float q1 = T21[4]*p0 + T21[5]*p1 + T21[6] *p2v + T21[7];
            float q2 = T21[8]*p0 + T21[9]*p1 + T21[10]*p2v + T21[11];
            float4 pp = *(const float4*)(g_p2 + (size_t)(b * NPTS + i) * 4);
            float e0 = q0 - pp.x, e1 = q1 - pp.y, e2 = q2 - pp.z;
            float aa = w0[i], bb = w1[i], cc = w2[i];
            float d0 = w3[i], d1 = w4[i], d2 = w5[i];
            float u0 = e0 + aa * e1 + bb * e2;
            float u1 = e1 + cc * e2;
            float u2 = e2;
            float mah = __expf(d0)*u0*u0 + __expf(d1)*u1*u1 + __expf(d2)*u2*u2;
            if (mah < 10000.0f) { sm += mah; sd += d0 + d1 + d2; cnt += 1.f; }
        }
#pragma unroll
        for (int o = 16; o; o >>= 1) {
            sm  += __shfl_xor_sync(0xffffffffu, sm,  o);
            sd  += __shfl_xor_sync(0xffffffffu, sd,  o);
            cnt += __shfl_xor_sync(0xffffffffu, cnt, o);
        }
        if ((threadIdx.x & 31) == 0) {
            rs[threadIdx.x >> 5] = sm;
            rd[threadIdx.x >> 5] = sd;
            rc[threadIdx.x >> 5] = cnt;
        }
        __syncthreads();
        if (threadIdx.x == 0) {
            float S = 0.f, D = 0.f, C = 0.f;
            for (int w = 0; w < WARPS; w++) { S += rs[w]; D += rd[w]; C += rc[w]; }
            acc += (S - D) / fmaxf(C, 1.f);
        }
        __syncthreads();
    }
    if (threadIdx.x == 0) {
        out[0] = acc;
        g_ctr = 0;        // self-reset: graph-replay safe
    }
}

// ================= launch ====================================================
extern "C" void kernel_launch(void* const* d_in, const int* in_sizes, int n_in,
                              void* d_out, int out_size)
{
    const float* src   = (const float*)d_in[0];   // (4,3,5760)
    const float* tgt   = (const float*)d_in[1];   // (4,3,5760)
    const float* wts   = (const float*)d_in[2];   // (4,6,5760)
    const float* match = (const float*)d_in[3];   // (4,5760,5760)
    const float* Tiv   = (const float*)d_in[4];   // (8,4,4)
    const int*   pmask = (const int*)d_in[5];     // (8,5760)

    const int dynbytes = WARPS * DPTH * ROWB;     // 80 KB ring per block
    static int configured = 0;
    if (!configured) {
        cudaFuncSetAttribute(k_main, cudaFuncAttributeMaxDynamicSharedMemorySize, dynbytes);
        configured = 1;
    }

    dim3 g1(NCT, NRT, BATCH);                     // 9 x 24 x 4 = 864 blocks
    k_main<<<g1, TPB, dynbytes>>>(match, tgt, pmask);

    const int total2 = 2 * BATCH * NPTS;
    k_merge_loss<<<(total2 + TPB - 1) / TPB, TPB>>>(src, wts, Tiv, pmask, (float*)d_out);
}

// round 5
// speedup vs baseline: 1.7561x; 1.7561x over previous
#include <cuda_runtime.h>
#include <cstdint>

#define NPTS  5760
#define BATCH 4
#define CT    640            // columns per tile
#define NCT   9              // 5760 / 640
#define RT    240            // rows per block
#define NRT   24             // 5760 / 240
#define WARPS 10
#define TPB   320
#define RPW   24             // rows per warp (240 / 10)
#define EPL   20             // elements per lane (640 / 32)
#define DPTH  4              // cp.async ring depth (rows staged per warp)
#define ROWB  (CT * 4)       // 2560 bytes per staged row
#define LBLK  8              // loss blocks per batch
#define TEMPF 100.0f
#define NEGV  -1e30f
#define TH_OFF 0.30f         // exp cutoff: e^(-30) ~ 1e-13 relative

// -------- scratch (static device globals; no allocation allowed) --------
__device__ float g_rowpart[BATCH * NCT * NPTS * 8];   // per (b,tile,row): m,s,px,py,pz,argcol
__device__ float g_colV[BATCH * NRT * NPTS];          // per (b,rowtile,col): best value
__device__ int   g_colR[BATCH * NRT * NPTS];          // per (b,rowtile,col): best row
__device__ float g_p2[BATCH * NPTS * 4];              // points2 (xyz, pad)
__device__ int   g_i21[BATCH * NPTS];                 // ind2to1
__device__ int   g_i12[BATCH * NPTS];                 // ind1to2
__device__ float4 g_part[BATCH * LBLK];               // loss partials (sm, sd, cnt)
__device__ unsigned g_ctr;                            // ticket counter (self-resetting)

// -------- warp collectives --------
// order-preserving f32 -> u32 map (exact for all finite floats, +-inf)
__device__ __forceinline__ unsigned f2ord(float f) {
    unsigned u = __float_as_uint(f);
    return (u & 0x80000000u) ? ~u : (u | 0x80000000u);
}
__device__ __forceinline__ float ord2f(unsigned u) {
    unsigned v = (u & 0x80000000u) ? (u & 0x7fffffffu) : ~u;
    return __uint_as_float(v);
}
__device__ __forceinline__ unsigned warp_max_u32(unsigned v) {
    unsigned r;
    asm volatile("redux.sync.max.u32 %0, %1, 0xffffffff;" : "=r"(r) : "r"(v));
    return r;
}
__device__ __forceinline__ unsigned warp_min_u32(unsigned v) {
    unsigned r;
    asm volatile("redux.sync.min.u32 %0, %1, 0xffffffff;" : "=r"(r) : "r"(v));
    return r;
}

// -------- cp.async helpers --------
__device__ __forceinline__ void cp16(uint32_t sdst, const void* gsrc) {
    asm volatile("cp.async.cg.shared.global [%0], [%1], 16;" :: "r"(sdst), "l"(gsrc));
}
__device__ __forceinline__ void cp_commit() {
    asm volatile("cp.async.commit_group;" ::: "memory");
}
template<int N> __device__ __forceinline__ void cp_wait() {
    asm volatile("cp.async.wait_group %0;" :: "n"(N) : "memory");
}
__device__ __forceinline__ void stage_row(uint32_t sdst, const float* grow, int lane) {
#pragma unroll
    for (int k = 0; k < 5; k++)
        cp16(sdst + k * 512, (const void*)(grow + k * 128 + lane * 4));
    cp_commit();
}

// ================= K1: single streaming pass over valid rows ================
extern __shared__ char dynsmem[];

__global__ void __launch_bounds__(TPB, 2) k_main(const float* __restrict__ match,
                                                 const float* __restrict__ tgt,
                                                 const int*   __restrict__ pmask)
{
    const int b    = blockIdx.z;
    const int tile = blockIdx.x;
    const int rt   = blockIdx.y;
    const int warp = threadIdx.x >> 5;
    const int lane = threadIdx.x & 31;
    const int col0 = tile * CT;
    const int row0 = rt * RT;

    const int* m1p = pmask + (size_t)(2 * b) * NPTS;
    const int* m2p = pmask + (size_t)(2 * b + 1) * NPTS;

    const uint32_t sbase = (uint32_t)__cvta_generic_to_shared(dynsmem);
    const uint32_t mybuf = sbase + (uint32_t)(warp * DPTH) * ROWB + lane * 16;

    float ma[EPL];    // column mask add: 0 or -1e30
    float cbv[EPL];   // column-best value
    int   cbr[EPL];   // column-best row
#pragma unroll
    for (int k = 0; k < 5; k++) {
        int4 mm = *(const int4*)(m2p + col0 + k * 128 + lane * 4);
        ma[4*k+0] = mm.x ? 0.f : NEGV;
        ma[4*k+1] = mm.y ? 0.f : NEGV;
        ma[4*k+2] = mm.z ? 0.f : NEGV;
        ma[4*k+3] = mm.w ? 0.f : NEGV;
    }
#pragma unroll
    for (int e = 0; e < EPL; e++) { cbv[e] = -INFINITY; cbr[e] = 0; }

    const float* tgx = tgt + (size_t)(b * 3 + 0) * NPTS;
    const float* tgy = tgt + (size_t)(b * 3 + 1) * NPTS;
    const float* tgz = tgt + (size_t)(b * 3 + 2) * NPTS;

    const int rbeg = row0 + warp * RPW;
    bool vb = (lane < RPW) ? (m1p[rbeg + lane] != 0) : false;
    const unsigned mbits = __ballot_sync(0xffffffffu, vb);
    const int nval = __popc(mbits);

    // per-lane: index of (lane+1)-th set bit of mbits
    int rl = 0;
    {
        int need = lane + 1;
        for (int bb = 0; bb < RPW; bb++)
            if ((mbits >> bb) & 1u) { if (--need == 0) { rl = bb; break; } }
    }

    const float* mbase = match + ((size_t)b * NPTS) * NPTS + col0;

#pragma unroll
    for (int i = 0; i < DPTH; i++) {
        if (i < nval) {
            int rr = rbeg + __shfl_sync(0xffffffffu, rl, i);
            stage_row(mybuf + i * ROWB, mbase + (size_t)rr * NPTS, lane);
        } else {
            cp_commit();
        }
    }

    for (int i = 0; i < nval; i++) {
        cp_wait<DPTH - 1>();
        const int r = rbeg + __shfl_sync(0xffffffffu, rl, i);
        const char* buf = dynsmem + (size_t)(warp * DPTH + (i % DPTH)) * ROWB + lane * 16;

        float v[EPL];
#pragma unroll
        for (int k = 0; k < 5; k++) {
            float4 t = *(const float4*)(buf + k * 512);
            v[4*k+0] = t.x; v[4*k+1] = t.y; v[4*k+2] = t.z; v[4*k+3] = t.w;
        }
        // column-best + lane max of masked values (4 parallel accumulators)
        float a0 = -INFINITY, a1 = -INFINITY, a2 = -INFINITY, a3 = -INFINITY;
#pragma unroll
        for (int k = 0; k < 5; k++) {
            int e = k * 4;
            if (v[e+0] > cbv[e+0]) { cbv[e+0] = v[e+0]; cbr[e+0] = r; }
            if (v[e+1] > cbv[e+1]) { cbv[e+1] = v[e+1]; cbr[e+1] = r; }
            if (v[e+2] > cbv[e+2]) { cbv[e+2] = v[e+2]; cbr[e+2] = r; }
            if (v[e+3] > cbv[e+3]) { cbv[e+3] = v[e+3]; cbr[e+3] = r; }
            a0 = fmaxf(a0, v[e+0] + ma[e+0]);
            a1 = fmaxf(a1, v[e+1] + ma[e+1]);
            a2 = fmaxf(a2, v[e+2] + ma[e+2]);
            a3 = fmaxf(a3, v[e+3] + ma[e+3]);
        }
        const float lm = fmaxf(fmaxf(a0, a1), fmaxf(a2, a3));
        const float wm = ord2f(warp_max_u32(f2ord(lm)));   // 1 redux vs 5-SHFL chain
        const float th = wm - TH_OFF;

        float s = 0.f, px = 0.f, py = 0.f, pz = 0.f;
        unsigned bc = 0x7fffffffu;
        const unsigned bal = __ballot_sync(0xffffffffu, lm > th);
        if (lm > th) {
#pragma unroll
            for (int e = 0; e < EPL; e++) {
                float vmv = v[e] + ma[e];
                if (vmv > th) {
                    float w = __expf((vmv - wm) * TEMPF);
                    int c = col0 + (e >> 2) * 128 + lane * 4 + (e & 3);
                    s  += w;
                    px += w * tgx[c];
                    py += w * tgy[c];
                    pz += w * tgz[c];
                    if (vmv == wm) bc = min(bc, (unsigned)c);
                }
            }
        }
        if (__popc(bal) == 1) {
            int sl = __ffs(bal) - 1;
            s  = __shfl_sync(0xffffffffu, s,  sl);
            px = __shfl_sync(0xffffffffu, px, sl);
            py = __shfl_sync(0xffffffffu, py, sl);
            pz = __shfl_sync(0xffffffffu, pz, sl);
            bc = __shfl_sync(0xffffffffu, bc, sl);
        } else {
#pragma unroll
            for (int o = 16; o; o >>= 1) {
                s  += __shfl_xor_sync(0xffffffffu, s,  o);
                px += __shfl_xor_sync(0xffffffffu, px, o);
                py += __shfl_xor_sync(0xffffffffu, py, o);
                pz += __shfl_xor_sync(0xffffffffu, pz, o);
            }
            bc = warp_min_u32(bc);
        }
        if (lane == 0) {
            float* out = g_rowpart + ((size_t)(b * NCT + tile) * NPTS + r) * 8;
            *(float4*)(out)     = make_float4(wm, s, px, py);
            *(float4*)(out + 4) = make_float4(pz, __int_as_float((int)bc), 0.f, 0.f);
        }

        int j = i + DPTH;
        if (j < nval) {
            int rr = rbeg + __shfl_sync(0xffffffffu, rl, j);
            stage_row(mybuf + (j % DPTH) * ROWB, mbase + (size_t)rr * NPTS, lane);
        } else {
            cp_commit();
        }
    }
    cp_wait<0>();
    __syncthreads();

    // block-level column-best merge (warps ascending => first-row tie-break)
    float* sv = (float*)dynsmem;                       // [WARPS][CT]
    int*   sr = (int*)(dynsmem + WARPS * CT * 4);      // [WARPS][CT]
#pragma unroll
    for (int e = 0; e < EPL; e++) {
        int cl = (e >> 2) * 128 + lane * 4 + (e & 3);
        sv[warp * CT + cl] = cbv[e];
        sr[warp * CT + cl] = cbr[e];
    }
    __syncthreads();
    for (int c = threadIdx.x; c < CT; c += TPB) {
        float bv = -INFINITY; int br = 0;
#pragma unroll
        for (int w = 0; w < WARPS; w++) {
            float vv = sv[w * CT + c];
            if (vv > bv) { bv = vv; br = sr[w * CT + c]; }
        }
        size_t o = (size_t)(b * NRT + rt) * NPTS + col0 + c;
        g_colV[o] = bv;
        g_colR[o] = br;
    }
}

// ================= K2: merge row tiles + column tiles (fully parallel) ======
__global__ void __launch_bounds__(256) k_merge(const int* __restrict__ pmask)
{
    const int gid = blockIdx.x * 256 + threadIdx.x;
    const int total = BATCH * NPTS;
    if (gid < total) {
        const int b = gid / NPTS, r = gid - b * NPTS;
        if (!pmask[(size_t)(2 * b) * NPTS + r]) return;
        float4 A[NCT], Bv[NCT];
#pragma unroll
        for (int t = 0; t < NCT; t++) {
            const float* base = g_rowpart + ((size_t)(b * NCT + t) * NPTS + r) * 8;
            A[t]  = *(const float4*)(base);
            Bv[t] = *(const float4*)(base + 4);
        }
        float M = -INFINITY; int argc = 0;
#pragma unroll
        for (int t = 0; t < NCT; t++)
            if (A[t].x > M) { M = A[t].x; argc = __float_as_int(Bv[t].y); }
        float S = 0.f, Px = 0.f, Py = 0.f, Pz = 0.f;
#pragma unroll
        for (int t = 0; t < NCT; t++) {
            float w = __expf((A[t].x - M) * TEMPF);
            S  += A[t].y * w;
            Px += A[t].z * w;
            Py += A[t].w * w;
            Pz += Bv[t].x * w;
        }
        float inv = 1.f / S;
        *(float4*)(g_p2 + (size_t)gid * 4) = make_float4(Px * inv, Py * inv, Pz * inv, 0.f);
        g_i21[gid] = argc;
    } else if (gid < 2 * total) {
        const int g2 = gid - total;
        const int b = g2 / NPTS, c = g2 - b * NPTS;
        float bv = -INFINITY; int br = 0;
#pragma unroll
        for (int t = 0; t < NRT; t++) {
            size_t o = (size_t)(b * NRT + t) * NPTS + c;
            float vv = g_colV[o];
            if (vv > bv) { bv = vv; br = g_colR[o]; }
        }
        g_i12[g2] = br;
    }
}

// ================= K3: parallel loss partials + tiny ticket finish ==========
__global__ void __launch_bounds__(256) k_loss(const float* __restrict__ src,
                                              const float* __restrict__ wts,
                                              const float* __restrict__ Tiv,
                                              const int*   __restrict__ pmask,
                                              float* __restrict__ out)
{
    const int b   = blockIdx.x / LBLK;
    const int blk = blockIdx.x % LBLK;
    const int CH  = NPTS / LBLK;                 // 720 points per block

    __shared__ float T21[12];
    if (threadIdx.x == 0) {
        const float* Ts = Tiv + (size_t)(2 * b) * 16;
        const float* Tt = Tiv + (size_t)(2 * b + 1) * 16;
        float A[3][4];
        for (int i = 0; i < 3; i++) {
            for (int k = 0; k < 3; k++) A[i][k] = Tt[k * 4 + i];
            A[i][3] = -(Tt[0*4+i]*Tt[3] + Tt[1*4+i]*Tt[7] + Tt[2*4+i]*Tt[11]);
        }
        for (int i = 0; i < 3; i++)
            for (int j = 0; j < 4; j++)
                T21[i*4+j] = A[i][0]*Ts[j] + A[i][1]*Ts[4+j]
                           + A[i][2]*Ts[8+j] + A[i][3]*Ts[12+j];
    }
    __syncthreads();

    const float* sx = src + (size_t)(b * 3 + 0) * NPTS;
    const float* sy = src + (size_t)(b * 3 + 1) * NPTS;
    const float* sz = src + (size_t)(b * 3 + 2) * NPTS;
    const float* w0 = wts + (size_t)(b * 6 + 0) * NPTS;
    const float* w1 = wts + (size_t)(b * 6 + 1) * NPTS;
    const float* w2 = wts + (size_t)(b * 6 + 2) * NPTS;
    const float* w3 = wts + (size_t)(b * 6 + 3) * NPTS;
    const float* w4 = wts + (size_t)(b * 6 + 4) * NPTS;
    const float* w5 = wts + (size_t)(b * 6 + 5) * NPTS;
    const int*   m1  = pmask + (size_t)(2 * b) * NPTS;
    const int*   i21 = g_i21 + b * NPTS;
    const int*   i12 = g_i12 + b * NPTS;

    float sm = 0.f, sd = 0.f, cnt = 0.f;
    const int i0 = blk * CH;
    for (int i = i0 + threadIdx.x; i < i0 + CH; i += 256) {
        if (!m1[i]) continue;
        int j = i21[i];
        if (i12[j] != i) continue;
        float p0 = sx[i], p1 = sy[i], p2v = sz[i];
        float q0 = T21[0]*p0 + T21[1]*p1 + T21[2] *p2v + T21[3];
        float q1 = T21[4]*p0 + T21[5]*p1 + T21[6] *p2v + T21[7];
        float q2 = T21[8]*p0 + T21[9]*p1 + T21[10]*p2v + T21[11];
        float4 pp = *(const float4*)(g_p2 + (size_t)(b * NPTS + i) * 4);
        float e0 = q0 - pp.x, e1 = q1 - pp.y, e2 = q2 - pp.z;
        float aa = w0[i], bb = w1[i], cc = w2[i];
        float d0 = w3[i], d1 = w4[i], d2 = w5[i];
        float u0 = e0 + aa * e1 + bb * e2;
        float u1 = e1 + cc * e2;
        float u2 = e2;
        float mah = __expf(d0)*u0*u0 + __expf(d1)*u1*u1 + __expf(d2)*u2*u2;
        if (mah < 10000.0f) { sm += mah; sd += d0 + d1 + d2; cnt += 1.f; }
    }
#pragma unroll
    for (int o = 16; o; o >>= 1) {
        sm  += __shfl_xor_sync(0xffffffffu, sm,  o);
        sd  += __shfl_xor_sync(0xffffffffu, sd,  o);
        cnt += __shfl_xor_sync(0xffffffffu, cnt, o);
    }
    __shared__ float rs[8], rd[8], rc[8];
    if ((threadIdx.x & 31) == 0) {
        rs[threadIdx.x >> 5] = sm;
        rd[threadIdx.x >> 5] = sd;
        rc[threadIdx.x >> 5] = cnt;
    }
    __syncthreads();
    if (threadIdx.x == 0) {
        float S = 0.f, D = 0.f, C = 0.f;
        for (int w = 0; w < 8; w++) { S += rs[w]; D += rd[w]; C += rc[w]; }
        g_part[b * LBLK + blk] = make_float4(S, D, C, 0.f);
    }

    // ticket: last block finishes (tiny deterministic sum over 32 partials)
    __threadfence();
    __syncthreads();
    __shared__ unsigned amlast;
    if (threadIdx.x == 0)
        amlast = (atomicAdd(&g_ctr, 1u) == gridDim.x - 1);
    __syncthreads();
    if (!amlast) return;
    __threadfence();

    if (threadIdx.x == 0) {
        float acc = 0.f;
        for (int bb = 0; bb < BATCH; bb++) {
            float S = 0.f, D = 0.f, C = 0.f;
            for (int k = 0; k < LBLK; k++) {
                float4 p = g_part[bb * LBLK + k];
                S += p.x; D += p.y; C += p.z;
            }
            acc += (S - D) / fmaxf(C, 1.f);
        }
        out[0] = acc;
        g_ctr = 0;
    }
}

// ================= launch ====================================================
extern "C" void kernel_launch(void* const* d_in, const int* in_sizes, int n_in,
                              void* d_out, int out_size)
{
    const float* src   = (const float*)d_in[0];   // (4,3,5760)
    const float* tgt   = (const float*)d_in[1];   // (4,3,5760)
    const float* wts   = (const float*)d_in[2];   // (4,6,5760)
    const float* match = (const float*)d_in[3];   // (4,5760,5760)
    const float* Tiv   = (const float*)d_in[4];   // (8,4,4)
    const int*   pmask = (const int*)d_in[5];     // (8,5760)

    const int dynbytes = WARPS * DPTH * ROWB;     // 100 KB ring per block
    static int configured = 0;
    if (!configured) {
        cudaFuncSetAttribute(k_main, cudaFuncAttributeMaxDynamicSharedMemorySize, dynbytes);
        configured = 1;
    }

    dim3 g1(NCT, NRT, BATCH);                     // 9 x 24 x 4 = 864 blocks
    k_main<<<g1, TPB, dynbytes>>>(match, tgt, pmask);

    const int total2 = 2 * BATCH * NPTS;
    k_merge<<<(total2 + 255) / 256, 256>>>(pmask);
    k_loss<<<BATCH * LBLK, 256>>>(src, wts, Tiv, pmask, (float*)d_out);
}